// round 3
// baseline (speedup 1.0000x reference)
#include <cuda_runtime.h>

#define TB      32      // batch rows per CTA
#define RPAD    33      // row stride (floats) of [feat][row] activation buffers
#define KT      8       // k-chunk staged per step
#define WPAD    260     // weight stage row stride (floats)
#define NTHREADS 256
#define OMEGA_F 30.0f

// ---------- f32x2 packed math (Blackwell FFMA2: 2x fp32 FMA throughput) ----------
static __device__ __forceinline__ unsigned long long pack2(float a, float b) {
    unsigned long long r;
    asm("mov.b64 %0, {%1, %2};" : "=l"(r) : "f"(a), "f"(b));
    return r;
}
static __device__ __forceinline__ void unpack2(unsigned long long v, float &a, float &b) {
    asm("mov.b64 {%0, %1}, %2;" : "=f"(a), "=f"(b) : "l"(v));
}
static __device__ __forceinline__ unsigned long long fma2(unsigned long long a,
                                                          unsigned long long b,
                                                          unsigned long long c) {
    unsigned long long d;
    asm("fma.rn.f32x2 %0, %1, %2, %3;" : "=l"(d) : "l"(a), "l"(b), "l"(c));
    return d;
}

// Shared memory layout (in floats)
#define SM_BUFE 0
#define SM_BUFT (256 * RPAD)
#define SM_BUFU (2 * 256 * RPAD)
#define SM_WBUF (3 * 256 * RPAD)
#define SM_XS   (SM_WBUF + KT * WPAD)
#define SM_PROB (SM_XS + 4 * RPAD)
#define SM_YACC (SM_PROB + 7 * TB)
#define SM_SCR  (SM_YACC + TB)
#define SM_TOTAL (SM_SCR + 8 * TB)

// ---------------------------------------------------------------------------
// Register-tiled fused GEMM layer over one CTA tile of TB=32 rows.
//   in  : smem activations, [K][RPAD] feature-major
//   W   : global weights, [N][K] row-major
//   out : smem activations, [N][RPAD]
//   ACT : 0 = sin(OMEGA*z), 1 = relu(z), 2 = relu(z + res)
// Each thread: 4 rows (warp-owned) x 8 cols (4 f32x2 column pairs, lane-interleaved).
// Weights staged KT=8 rows at a time into wbuf with register prefetch of next chunk.
// Requires K % KT == 0, N in {128, 256}.
// ---------------------------------------------------------------------------
template <int NP2, int ACT>
static __device__ __forceinline__ void gemm16(
    const float* __restrict__ in, int K,
    const float* __restrict__ W, const float* __restrict__ bias,
    float* __restrict__ out, float* __restrict__ wbuf,
    const float* __restrict__ res)
{
    constexpr int N   = NP2 * 64;
    constexpr int LDN = KT * N / NTHREADS;   // global loads per thread per chunk (4 or 8)

    const int tid  = threadIdx.x;
    const int lane = tid & 31;
    const int warp = tid >> 5;
    const int r0   = warp * 4;

    unsigned long long acc[4][NP2];
#pragma unroll
    for (int i = 0; i < 4; i++)
#pragma unroll
        for (int j = 0; j < NP2; j++) acc[i][j] = 0ull;

    // prefetch chunk 0 into registers
    float wr[LDN];
#pragma unroll
    for (int l = 0; l < LDN; l++) {
        int idx = tid + NTHREADS * l;
        int n = idx >> 3, kk = idx & 7;
        wr[l] = W[n * K + kk];
    }

    for (int k0 = 0; k0 < K; k0 += KT) {
        // commit prefetched chunk to smem
#pragma unroll
        for (int l = 0; l < LDN; l++) {
            int idx = tid + NTHREADS * l;
            int n = idx >> 3, kk = idx & 7;
            wbuf[kk * WPAD + n] = wr[l];
        }
        __syncthreads();

        // issue next chunk's global loads (latency hidden by compute below)
        if (k0 + KT < K) {
#pragma unroll
            for (int l = 0; l < LDN; l++) {
                int idx = tid + NTHREADS * l;
                int n = idx >> 3, kk = idx & 7;
                wr[l] = W[n * K + (k0 + KT) + kk];
            }
        }

#pragma unroll
        for (int kk = 0; kk < KT; kk++) {
            const float* arow = in + (k0 + kk) * RPAD + r0;
            unsigned long long a2[4];
#pragma unroll
            for (int i = 0; i < 4; i++) {
                float a = arow[i];                 // warp-broadcast LDS
                a2[i] = pack2(a, a);
            }
#pragma unroll
            for (int j = 0; j < NP2; j++) {
                unsigned long long w2 =
                    *(const unsigned long long*)(wbuf + kk * WPAD + 2 * (lane + 32 * j));
#pragma unroll
                for (int i = 0; i < 4; i++) acc[i][j] = fma2(a2[i], w2, acc[i][j]);
            }
        }
        __syncthreads();
    }

    // epilogue: bias + activation, store transposed [n][row]
#pragma unroll
    for (int j = 0; j < NP2; j++) {
        int n = 2 * (lane + 32 * j);
        float b0 = __ldg(bias + n), b1 = __ldg(bias + n + 1);
#pragma unroll
        for (int i = 0; i < 4; i++) {
            float z0, z1;
            unpack2(acc[i][j], z0, z1);
            z0 += b0; z1 += b1;
            if (ACT == 0) {
                z0 = __sinf(OMEGA_F * z0);
                z1 = __sinf(OMEGA_F * z1);
            } else if (ACT == 1) {
                z0 = fmaxf(z0, 0.0f);
                z1 = fmaxf(z1, 0.0f);
            } else {
                z0 = fmaxf(z0 + res[n * RPAD + r0 + i], 0.0f);
                z1 = fmaxf(z1 + res[(n + 1) * RPAD + r0 + i], 0.0f);
            }
            out[n * RPAD + r0 + i]       = z0;
            out[(n + 1) * RPAD + r0 + i] = z1;
        }
    }
    __syncthreads();
}

// Small-K variant (single staged chunk, K <= KT). Used for pol_s1 (K=4).
template <int NP2, int ACT>
static __device__ __forceinline__ void gemm_small(
    const float* __restrict__ in, int K,
    const float* __restrict__ W, const float* __restrict__ bias,
    float* __restrict__ out, float* __restrict__ wbuf)
{
    constexpr int N = NP2 * 64;
    const int tid  = threadIdx.x;
    const int lane = tid & 31;
    const int warp = tid >> 5;
    const int r0   = warp * 4;

    for (int idx = tid; idx < K * N; idx += NTHREADS) {
        int n = idx / K;
        int kk = idx - n * K;
        wbuf[kk * WPAD + n] = W[n * K + kk];
    }
    __syncthreads();

    unsigned long long acc[4][NP2];
#pragma unroll
    for (int i = 0; i < 4; i++)
#pragma unroll
        for (int j = 0; j < NP2; j++) acc[i][j] = 0ull;

    for (int kk = 0; kk < K; kk++) {
        const float* arow = in + kk * RPAD + r0;
        unsigned long long a2[4];
#pragma unroll
        for (int i = 0; i < 4; i++) {
            float a = arow[i];
            a2[i] = pack2(a, a);
        }
#pragma unroll
        for (int j = 0; j < NP2; j++) {
            unsigned long long w2 =
                *(const unsigned long long*)(wbuf + kk * WPAD + 2 * (lane + 32 * j));
#pragma unroll
            for (int i = 0; i < 4; i++) acc[i][j] = fma2(a2[i], w2, acc[i][j]);
        }
    }

#pragma unroll
    for (int j = 0; j < NP2; j++) {
        int n = 2 * (lane + 32 * j);
        float b0 = __ldg(bias + n), b1 = __ldg(bias + n + 1);
#pragma unroll
        for (int i = 0; i < 4; i++) {
            float z0, z1;
            unpack2(acc[i][j], z0, z1);
            z0 += b0; z1 += b1;
            if (ACT == 0) {
                z0 = __sinf(OMEGA_F * z0);
                z1 = __sinf(OMEGA_F * z1);
            } else {
                z0 = fmaxf(z0, 0.0f);
                z1 = fmaxf(z1, 0.0f);
            }
            out[n * RPAD + r0 + i]       = z0;
            out[(n + 1) * RPAD + r0 + i] = z1;
        }
    }
    __syncthreads();
}

// ---------------------------------------------------------------------------
__global__ void __launch_bounds__(NTHREADS, 2)
moe_inr_kernel(
    const float* __restrict__ x,
    const float* __restrict__ enc_s1_w, const float* __restrict__ enc_s1_b,
    const float* __restrict__ enc_s2_w, const float* __restrict__ enc_s2_b,
    const float* __restrict__ res_fc1_w, const float* __restrict__ res_fc1_b,
    const float* __restrict__ res_fc2_w, const float* __restrict__ res_fc2_b,
    const float* __restrict__ res_fc3_w, const float* __restrict__ res_fc3_b,
    const float* __restrict__ pol_s1_w, const float* __restrict__ pol_s1_b,
    const float* __restrict__ pol_s2_w, const float* __restrict__ pol_s2_b,
    const float* __restrict__ gate_w, const float* __restrict__ gate_b,
    const float* __restrict__ exp_s1_w, const float* __restrict__ exp_s1_b,
    const float* __restrict__ exp_s2_w, const float* __restrict__ exp_s2_b,
    const float* __restrict__ exp_fin_w, const float* __restrict__ exp_fin_b,
    float* __restrict__ out)
{
    extern __shared__ float smem[];
    float* bufE  = smem + SM_BUFE;
    float* bufT  = smem + SM_BUFT;
    float* bufU  = smem + SM_BUFU;
    float* wbuf  = smem + SM_WBUF;
    float* xs    = smem + SM_XS;
    float* probs = smem + SM_PROB;
    float* yacc  = smem + SM_YACC;
    float* scr   = smem + SM_SCR;

    const int tid = threadIdx.x;
    const long long rowbase = (long long)blockIdx.x * TB;

    // ---- load x tile: [4][RPAD] feature-major ----
    if (tid < TB * 4) {
        int r = tid >> 2, d = tid & 3;
        xs[d * RPAD + r] = x[(rowbase + r) * 4 + d];
    }
    __syncthreads();

    // ---- positional encoding -> bufT rows [0,TB): col = d*16 + f; f<8 sin, else cos ----
    for (int idx = tid; idx < 64 * TB; idx += NTHREADS) {
        int r = idx & (TB - 1), c = idx / TB;
        int d = c >> 4, f = c & 15;
        float freq = exp2f((float)(f & 7)) * 3.14159265358979323846f;
        float ang  = xs[d * RPAD + r] * freq;
        bufT[c * RPAD + r] = (f < 8) ? sinf(ang) : cosf(ang);
    }
    __syncthreads();

    // ---- encoder ----
    gemm16<2, 0>(bufT, 64,  enc_s1_w,  enc_s1_b,  bufU, wbuf, nullptr);   // sin -> [128]
    gemm16<4, 0>(bufU, 128, enc_s2_w,  enc_s2_b,  bufE, wbuf, nullptr);   // sin -> h [256]
    gemm16<2, 1>(bufE, 256, res_fc1_w, res_fc1_b, bufT, wbuf, nullptr);   // relu -> [128]
    gemm16<2, 1>(bufT, 128, res_fc2_w, res_fc2_b, bufU, wbuf, nullptr);   // relu -> [128]
    gemm16<4, 2>(bufU, 128, res_fc3_w, res_fc3_b, bufE, wbuf, bufE);      // relu(r3+h) -> enc_feat

    // ---- policy ----
    gemm_small<2, 0>(xs, 4,   pol_s1_w, pol_s1_b, bufT, wbuf);            // sin -> [128]
    gemm16<2, 0>(bufT, 128, pol_s2_w, pol_s2_b, bufU, wbuf, nullptr);     // sin -> pf [128]

    // ---- gate: logits over concat(enc_feat[256], pf[128]) ----
    // Gate weights (7*384 = 2688 floats) staged in bufT, which is dead here
    // (pol_s2 consumed it) and large enough (256*RPAD = 8448 floats).
    float* gbuf = bufT;
    for (int idx = tid; idx < 7 * 384; idx += NTHREADS) gbuf[idx] = gate_w[idx];
    __syncthreads();
    for (int idx = tid; idx < 7 * TB; idx += NTHREADS) {
        int r = idx & (TB - 1), c = idx / TB;
        const float* gw = gbuf + c * 384;
        float s = __ldg(gate_b + c);
        for (int k = 0; k < 256; k++) s += bufE[k * RPAD + r] * gw[k];
        for (int k = 0; k < 128; k++) s += bufU[k * RPAD + r] * gw[256 + k];
        probs[c * TB + r] = s;
    }
    __syncthreads();
    if (tid < TB) {
        int r = tid;
        float m = -1e30f;
        for (int c = 0; c < 7; c++) m = fmaxf(m, probs[c * TB + r]);
        float s = 0.0f, e[7];
        for (int c = 0; c < 7; c++) { e[c] = __expf(probs[c * TB + r] - m); s += e[c]; }
        float inv = 1.0f / s;
        for (int c = 0; c < 7; c++) probs[c * TB + r] = e[c] * inv;
        yacc[r] = 0.0f;
    }
    __syncthreads();

    // ---- experts ----
    for (int e = 0; e < 7; e++) {
        gemm16<4, 0>(bufE, 256, exp_s1_w + e * 65536, exp_s1_b + e * 256, bufT, wbuf, nullptr);
        gemm16<4, 0>(bufT, 256, exp_s2_w + e * 65536, exp_s2_b + e * 256, bufU, wbuf, nullptr);
        // final linear [256]->1, 8-way split reduction per row
        {
            int part = tid >> 5, r = tid & 31;
            const float* Wf = exp_fin_w + e * 256;
            float s = 0.0f;
            int k0 = part * 32;
            for (int k = k0; k < k0 + 32; k++) s += bufU[k * RPAD + r] * __ldg(Wf + k);
            scr[part * TB + r] = s;
        }
        __syncthreads();
        if (tid < TB) {
            int r = tid;
            float pred = __ldg(exp_fin_b + e);
#pragma unroll
            for (int p = 0; p < 8; p++) pred += scr[p * TB + r];
            yacc[r] += probs[e * TB + r] * pred;
        }
        __syncthreads();
    }

    if (tid < TB) out[rowbase + tid] = yacc[tid];
}

// ---------------------------------------------------------------------------
extern "C" void kernel_launch(void* const* d_in, const int* in_sizes, int n_in,
                              void* d_out, int out_size)
{
    const float* x         = (const float*)d_in[0];
    const float* enc_s1_w  = (const float*)d_in[1];
    const float* enc_s1_b  = (const float*)d_in[2];
    const float* enc_s2_w  = (const float*)d_in[3];
    const float* enc_s2_b  = (const float*)d_in[4];
    const float* res_fc1_w = (const float*)d_in[5];
    const float* res_fc1_b = (const float*)d_in[6];
    const float* res_fc2_w = (const float*)d_in[7];
    const float* res_fc2_b = (const float*)d_in[8];
    const float* res_fc3_w = (const float*)d_in[9];
    const float* res_fc3_b = (const float*)d_in[10];
    const float* pol_s1_w  = (const float*)d_in[11];
    const float* pol_s1_b  = (const float*)d_in[12];
    const float* pol_s2_w  = (const float*)d_in[13];
    const float* pol_s2_b  = (const float*)d_in[14];
    const float* gate_w    = (const float*)d_in[15];
    const float* gate_b    = (const float*)d_in[16];
    const float* exp_s1_w  = (const float*)d_in[17];
    const float* exp_s1_b  = (const float*)d_in[18];
    const float* exp_s2_w  = (const float*)d_in[19];
    const float* exp_s2_b  = (const float*)d_in[20];
    const float* exp_fin_w = (const float*)d_in[21];
    const float* exp_fin_b = (const float*)d_in[22];

    int B = in_sizes[0] / 4;
    int grid = B / TB;
    size_t shmem = (size_t)SM_TOTAL * sizeof(float);

    cudaFuncSetAttribute(moe_inr_kernel,
                         cudaFuncAttributeMaxDynamicSharedMemorySize, (int)shmem);

    moe_inr_kernel<<<grid, NTHREADS, shmem>>>(
        x, enc_s1_w, enc_s1_b, enc_s2_w, enc_s2_b,
        res_fc1_w, res_fc1_b, res_fc2_w, res_fc2_b, res_fc3_w, res_fc3_b,
        pol_s1_w, pol_s1_b, pol_s2_w, pol_s2_b, gate_w, gate_b,
        exp_s1_w, exp_s1_b, exp_s2_w, exp_s2_b, exp_fin_w, exp_fin_b,
        (float*)d_out);
}

// round 4
// speedup vs baseline: 1.1200x; 1.1200x over previous
#include <cuda_runtime.h>

#define TB      32      // batch rows per CTA
#define RPAD    34      // row stride (floats), even => 8B-aligned float2 rows
#define KT      8       // k-chunk staged per step
#define WPAD    258     // weight stage row stride (floats)
#define NTHREADS 128
#define OMEGA_F 30.0f

// ---------- f32x2 packed math (Blackwell FFMA2: 2x fp32 FMA throughput) ----------
static __device__ __forceinline__ unsigned long long pack2(float a, float b) {
    unsigned long long r;
    asm("mov.b64 %0, {%1, %2};" : "=l"(r) : "f"(a), "f"(b));
    return r;
}
static __device__ __forceinline__ void unpack2(unsigned long long v, float &a, float &b) {
    asm("mov.b64 {%0, %1}, %2;" : "=f"(a), "=f"(b) : "l"(v));
}
static __device__ __forceinline__ unsigned long long fma2(unsigned long long a,
                                                          unsigned long long b,
                                                          unsigned long long c) {
    unsigned long long d;
    asm("fma.rn.f32x2 %0, %1, %2, %3;" : "=l"(d) : "l"(a), "l"(b), "l"(c));
    return d;
}

// Shared memory layout (in floats)
#define SM_BUFE 0
#define SM_BUFT (256 * RPAD)
#define SM_BUFU (2 * 256 * RPAD)
#define SM_WBUF (3 * 256 * RPAD)
#define SM_XS   (SM_WBUF + KT * WPAD)
#define SM_PROB (SM_XS + 4 * RPAD)
#define SM_YACC (SM_PROB + 7 * TB)
#define SM_SCR  (SM_YACC + TB)
#define SM_TOTAL (SM_SCR + 4 * TB)

// ---------------------------------------------------------------------------
// Register-tiled fused GEMM layer over one CTA tile of TB=32 rows.
//   in  : smem activations, [K][RPAD] feature-major
//   W   : global weights, [N][K] row-major
//   out : smem activations, [N][RPAD]
//   ACT : 0 = sin(OMEGA*z), 1 = relu(z), 2 = relu(z + res)
// f32x2 pairing = (2 rows x 1 col): a loads are broadcast LDS.64 of two
// adjacent rows; w loads are conflict-free stride-1 scalars (dup'd into a
// pair register); epilogue stores are aligned float2.
// Each thread: 8 rows (warp-owned, 4 row-pairs) x NC cols (n = lane + 32*j).
// NC = N/32. Requires K % KT == 0.
// ---------------------------------------------------------------------------
template <int NC, int ACT>
static __device__ __forceinline__ void gemm_layer(
    const float* __restrict__ in, int K,
    const float* __restrict__ W, const float* __restrict__ bias,
    float* __restrict__ out, float* __restrict__ wbuf,
    const float* __restrict__ res)
{
    constexpr int N   = NC * 32;
    constexpr int LDN = KT * N / NTHREADS;   // global loads per thread per chunk

    const int tid  = threadIdx.x;
    const int lane = tid & 31;
    const int warp = tid >> 5;
    const int r0   = warp * 8;

    unsigned long long acc[4][NC];
#pragma unroll
    for (int i = 0; i < 4; i++)
#pragma unroll
        for (int j = 0; j < NC; j++) acc[i][j] = 0ull;

    // prefetch chunk 0 into registers
    float wr[LDN];
#pragma unroll
    for (int l = 0; l < LDN; l++) {
        int idx = tid + NTHREADS * l;
        int n = idx >> 3, kk = idx & 7;
        wr[l] = W[n * K + kk];
    }

    for (int k0 = 0; k0 < K; k0 += KT) {
        // commit prefetched chunk to smem
#pragma unroll
        for (int l = 0; l < LDN; l++) {
            int idx = tid + NTHREADS * l;
            int n = idx >> 3, kk = idx & 7;
            wbuf[kk * WPAD + n] = wr[l];
        }
        __syncthreads();

        // issue next chunk's global loads (latency hidden by compute below)
        if (k0 + KT < K) {
#pragma unroll
            for (int l = 0; l < LDN; l++) {
                int idx = tid + NTHREADS * l;
                int n = idx >> 3, kk = idx & 7;
                wr[l] = W[n * K + (k0 + KT) + kk];
            }
        }

#pragma unroll
        for (int kk = 0; kk < KT; kk++) {
            const float* arow = in + (k0 + kk) * RPAD + r0;
            unsigned long long a2[4];
#pragma unroll
            for (int i = 0; i < 4; i++)          // broadcast LDS.64: rows (r0+2i, r0+2i+1)
                a2[i] = *(const unsigned long long*)(arow + 2 * i);
            const float* wrow = wbuf + kk * WPAD + lane;
#pragma unroll
            for (int j = 0; j < NC; j++) {
                float w = wrow[32 * j];          // conflict-free stride-1 LDS.32
                unsigned long long wd = pack2(w, w);
#pragma unroll
                for (int i = 0; i < 4; i++) acc[i][j] = fma2(a2[i], wd, acc[i][j]);
            }
        }
        __syncthreads();
    }

    // epilogue: bias + activation, store transposed [n][row] as float2
#pragma unroll
    for (int j = 0; j < NC; j++) {
        int n = lane + 32 * j;
        float b = __ldg(bias + n);
#pragma unroll
        for (int i = 0; i < 4; i++) {
            float z0, z1;
            unpack2(acc[i][j], z0, z1);
            z0 += b; z1 += b;
            if (ACT == 0) {
                z0 = __sinf(OMEGA_F * z0);
                z1 = __sinf(OMEGA_F * z1);
            } else if (ACT == 1) {
                z0 = fmaxf(z0, 0.0f);
                z1 = fmaxf(z1, 0.0f);
            } else {
                const float* rp = res + n * RPAD + r0 + 2 * i;
                z0 = fmaxf(z0 + rp[0], 0.0f);
                z1 = fmaxf(z1 + rp[1], 0.0f);
            }
            float2 v = make_float2(z0, z1);
            *(float2*)(out + n * RPAD + r0 + 2 * i) = v;
        }
    }
    __syncthreads();
}

// Small-K variant (single staged chunk, K <= KT). Used for pol_s1 (K=4).
template <int NC, int ACT>
static __device__ __forceinline__ void gemm_small(
    const float* __restrict__ in, int K,
    const float* __restrict__ W, const float* __restrict__ bias,
    float* __restrict__ out, float* __restrict__ wbuf)
{
    constexpr int N = NC * 32;
    const int tid  = threadIdx.x;
    const int lane = tid & 31;
    const int warp = tid >> 5;
    const int r0   = warp * 8;

    for (int idx = tid; idx < K * N; idx += NTHREADS) {
        int n = idx / K;
        int kk = idx - n * K;
        wbuf[kk * WPAD + n] = W[n * K + kk];
    }
    __syncthreads();

    unsigned long long acc[4][NC];
#pragma unroll
    for (int i = 0; i < 4; i++)
#pragma unroll
        for (int j = 0; j < NC; j++) acc[i][j] = 0ull;

    for (int kk = 0; kk < K; kk++) {
        const float* arow = in + kk * RPAD + r0;
        unsigned long long a2[4];
#pragma unroll
        for (int i = 0; i < 4; i++)
            a2[i] = *(const unsigned long long*)(arow + 2 * i);
        const float* wrow = wbuf + kk * WPAD + lane;
#pragma unroll
        for (int j = 0; j < NC; j++) {
            float w = wrow[32 * j];
            unsigned long long wd = pack2(w, w);
#pragma unroll
            for (int i = 0; i < 4; i++) acc[i][j] = fma2(a2[i], wd, acc[i][j]);
        }
    }

#pragma unroll
    for (int j = 0; j < NC; j++) {
        int n = lane + 32 * j;
        float b = __ldg(bias + n);
#pragma unroll
        for (int i = 0; i < 4; i++) {
            float z0, z1;
            unpack2(acc[i][j], z0, z1);
            z0 += b; z1 += b;
            if (ACT == 0) {
                z0 = __sinf(OMEGA_F * z0);
                z1 = __sinf(OMEGA_F * z1);
            } else {
                z0 = fmaxf(z0, 0.0f);
                z1 = fmaxf(z1, 0.0f);
            }
            float2 v = make_float2(z0, z1);
            *(float2*)(out + n * RPAD + r0 + 2 * i) = v;
        }
    }
    __syncthreads();
}

// ---------------------------------------------------------------------------
__global__ void __launch_bounds__(NTHREADS, 2)
moe_inr_kernel(
    const float* __restrict__ x,
    const float* __restrict__ enc_s1_w, const float* __restrict__ enc_s1_b,
    const float* __restrict__ enc_s2_w, const float* __restrict__ enc_s2_b,
    const float* __restrict__ res_fc1_w, const float* __restrict__ res_fc1_b,
    const float* __restrict__ res_fc2_w, const float* __restrict__ res_fc2_b,
    const float* __restrict__ res_fc3_w, const float* __restrict__ res_fc3_b,
    const float* __restrict__ pol_s1_w, const float* __restrict__ pol_s1_b,
    const float* __restrict__ pol_s2_w, const float* __restrict__ pol_s2_b,
    const float* __restrict__ gate_w, const float* __restrict__ gate_b,
    const float* __restrict__ exp_s1_w, const float* __restrict__ exp_s1_b,
    const float* __restrict__ exp_s2_w, const float* __restrict__ exp_s2_b,
    const float* __restrict__ exp_fin_w, const float* __restrict__ exp_fin_b,
    float* __restrict__ out)
{
    extern __shared__ float smem[];
    float* bufE  = smem + SM_BUFE;
    float* bufT  = smem + SM_BUFT;
    float* bufU  = smem + SM_BUFU;
    float* wbuf  = smem + SM_WBUF;
    float* xs    = smem + SM_XS;
    float* probs = smem + SM_PROB;
    float* yacc  = smem + SM_YACC;
    float* scr   = smem + SM_SCR;

    const int tid = threadIdx.x;
    const long long rowbase = (long long)blockIdx.x * TB;

    // ---- load x tile: [4][RPAD] feature-major (128 threads = TB*4 exactly) ----
    {
        int r = tid >> 2, d = tid & 3;
        xs[d * RPAD + r] = x[(rowbase + r) * 4 + d];
    }
    __syncthreads();

    // ---- positional encoding -> bufT rows [0,TB): col = d*16 + f; f<8 sin, else cos ----
    for (int idx = tid; idx < 64 * TB; idx += NTHREADS) {
        int r = idx & (TB - 1), c = idx / TB;
        int d = c >> 4, f = c & 15;
        float freq = exp2f((float)(f & 7)) * 3.14159265358979323846f;
        float ang  = xs[d * RPAD + r] * freq;
        bufT[c * RPAD + r] = (f < 8) ? sinf(ang) : cosf(ang);
    }
    __syncthreads();

    // ---- encoder ----
    gemm_layer<4, 0>(bufT, 64,  enc_s1_w,  enc_s1_b,  bufU, wbuf, nullptr);   // sin -> [128]
    gemm_layer<8, 0>(bufU, 128, enc_s2_w,  enc_s2_b,  bufE, wbuf, nullptr);   // sin -> h [256]
    gemm_layer<4, 1>(bufE, 256, res_fc1_w, res_fc1_b, bufT, wbuf, nullptr);   // relu -> [128]
    gemm_layer<4, 1>(bufT, 128, res_fc2_w, res_fc2_b, bufU, wbuf, nullptr);   // relu -> [128]
    gemm_layer<8, 2>(bufU, 128, res_fc3_w, res_fc3_b, bufE, wbuf, bufE);      // relu(r3+h) -> enc_feat

    // ---- policy ----
    gemm_small<4, 0>(xs, 4,   pol_s1_w, pol_s1_b, bufT, wbuf);                // sin -> [128]
    gemm_layer<4, 0>(bufT, 128, pol_s2_w, pol_s2_b, bufU, wbuf, nullptr);     // sin -> pf [128]

    // ---- gate: logits over concat(enc_feat[256], pf[128]) ----
    // Gate weights (7*384 = 2688 floats) staged in bufT (dead here, 8704 floats).
    float* gbuf = bufT;
    for (int idx = tid; idx < 7 * 384; idx += NTHREADS) gbuf[idx] = gate_w[idx];
    __syncthreads();
    for (int idx = tid; idx < 7 * TB; idx += NTHREADS) {
        int r = idx & (TB - 1), c = idx / TB;
        const float* gw = gbuf + c * 384;
        float s = __ldg(gate_b + c);
        for (int k = 0; k < 256; k++) s += bufE[k * RPAD + r] * gw[k];
        for (int k = 0; k < 128; k++) s += bufU[k * RPAD + r] * gw[256 + k];
        probs[c * TB + r] = s;
    }
    __syncthreads();
    if (tid < TB) {
        int r = tid;
        float m = -1e30f;
        for (int c = 0; c < 7; c++) m = fmaxf(m, probs[c * TB + r]);
        float s = 0.0f, e[7];
        for (int c = 0; c < 7; c++) { e[c] = __expf(probs[c * TB + r] - m); s += e[c]; }
        float inv = 1.0f / s;
        for (int c = 0; c < 7; c++) probs[c * TB + r] = e[c] * inv;
        yacc[r] = 0.0f;
    }
    __syncthreads();

    // ---- experts ----
    for (int e = 0; e < 7; e++) {
        gemm_layer<8, 0>(bufE, 256, exp_s1_w + e * 65536, exp_s1_b + e * 256, bufT, wbuf, nullptr);
        gemm_layer<8, 0>(bufT, 256, exp_s2_w + e * 65536, exp_s2_b + e * 256, bufU, wbuf, nullptr);
        // final linear [256]->1, 4-way split reduction per row
        {
            int part = tid >> 5, r = tid & 31;
            const float* Wf = exp_fin_w + e * 256;
            float s = 0.0f;
            int k0 = part * 64;
            for (int k = k0; k < k0 + 64; k++) s += bufU[k * RPAD + r] * __ldg(Wf + k);
            scr[part * TB + r] = s;
        }
        __syncthreads();
        if (tid < TB) {
            int r = tid;
            float pred = scr[r] + scr[TB + r] + scr[2 * TB + r] + scr[3 * TB + r]
                       + __ldg(exp_fin_b + e);
            yacc[r] += probs[e * TB + r] * pred;
        }
        __syncthreads();
    }

    if (tid < TB) out[rowbase + tid] = yacc[tid];
}

// ---------------------------------------------------------------------------
extern "C" void kernel_launch(void* const* d_in, const int* in_sizes, int n_in,
                              void* d_out, int out_size)
{
    const float* x         = (const float*)d_in[0];
    const float* enc_s1_w  = (const float*)d_in[1];
    const float* enc_s1_b  = (const float*)d_in[2];
    const float* enc_s2_w  = (const float*)d_in[3];
    const float* enc_s2_b  = (const float*)d_in[4];
    const float* res_fc1_w = (const float*)d_in[5];
    const float* res_fc1_b = (const float*)d_in[6];
    const float* res_fc2_w = (const float*)d_in[7];
    const float* res_fc2_b = (const float*)d_in[8];
    const float* res_fc3_w = (const float*)d_in[9];
    const float* res_fc3_b = (const float*)d_in[10];
    const float* pol_s1_w  = (const float*)d_in[11];
    const float* pol_s1_b  = (const float*)d_in[12];
    const float* pol_s2_w  = (const float*)d_in[13];
    const float* pol_s2_b  = (const float*)d_in[14];
    const float* gate_w    = (const float*)d_in[15];
    const float* gate_b    = (const float*)d_in[16];
    const float* exp_s1_w  = (const float*)d_in[17];
    const float* exp_s1_b  = (const float*)d_in[18];
    const float* exp_s2_w  = (const float*)d_in[19];
    const float* exp_s2_b  = (const float*)d_in[20];
    const float* exp_fin_w = (const float*)d_in[21];
    const float* exp_fin_b = (const float*)d_in[22];

    int B = in_sizes[0] / 4;
    int grid = B / TB;
    size_t shmem = (size_t)SM_TOTAL * sizeof(float);

    cudaFuncSetAttribute(moe_inr_kernel,
                         cudaFuncAttributeMaxDynamicSharedMemorySize, (int)shmem);

    moe_inr_kernel<<<grid, NTHREADS, shmem>>>(
        x, enc_s1_w, enc_s1_b, enc_s2_w, enc_s2_b,
        res_fc1_w, res_fc1_b, res_fc2_w, res_fc2_b, res_fc3_w, res_fc3_b,
        pol_s1_w, pol_s1_b, pol_s2_w, pol_s2_b, gate_w, gate_b,
        exp_s1_w, exp_s1_b, exp_s2_w, exp_s2_b, exp_fin_w, exp_fin_b,
        (float*)d_out);
}

// round 5
// speedup vs baseline: 1.1544x; 1.0307x over previous
#include <cuda_runtime.h>

#define TB      64      // batch rows per CTA
#define RPAD    66      // row stride (floats), even => aligned float2 row-pairs
#define NTHREADS 256
#define OMEGA_F 30.0f

// ---------- f32x2 packed math (Blackwell FFMA2) ----------
static __device__ __forceinline__ unsigned long long pack2(float a, float b) {
    unsigned long long r;
    asm("mov.b64 %0, {%1, %2};" : "=l"(r) : "f"(a), "f"(b));
    return r;
}
static __device__ __forceinline__ void unpack2(unsigned long long v, float &a, float &b) {
    asm("mov.b64 {%0, %1}, %2;" : "=f"(a), "=f"(b) : "l"(v));
}
static __device__ __forceinline__ unsigned long long fma2(unsigned long long a,
                                                          unsigned long long b,
                                                          unsigned long long c) {
    unsigned long long d;
    asm("fma.rn.f32x2 %0, %1, %2, %3;" : "=l"(d) : "l"(a), "l"(b), "l"(c));
    return d;
}

// ---------------------------------------------------------------------------
// Reformatted weight store: for each layer, layout [K/2][N] of ulonglong2
//   elem(k2, n) = { pack2(W[n][2k2],W[n][2k2]), pack2(W[n][2k2+1],W[n][2k2+1]) }
// Total 528,640 elements = 8.46 MB (L2-resident).
// ---------------------------------------------------------------------------
#define OFF_ENC1 0          //  64x128 -> 4096
#define OFF_ENC2 4096       // 128x256 -> 16384
#define OFF_RES1 20480      // 256x128 -> 16384
#define OFF_RES2 36864      // 128x128 -> 8192
#define OFF_RES3 45056      // 128x256 -> 16384
#define OFF_POL1 61440      //   4x128 -> 256
#define OFF_POL2 61696      // 128x128 -> 8192
#define OFF_EXP1 69888      // 7x 256x256 -> 229376
#define OFF_EXP2 299264     // 7x 256x256 -> 229376
#define WT_TOTAL 528640

__device__ ulonglong2 g_wt[WT_TOTAL];

// Reformat kernel: src is [NB][N][K] row-major; dst region is [NB][K/2][N].
__global__ void reformat_w(const float* __restrict__ src, int dst_off,
                           int N, int K, int NB)
{
    int idx = blockIdx.x * blockDim.x + threadIdx.x;
    int K2 = K / 2;
    int total = NB * K2 * N;
    if (idx >= total) return;
    int n  = idx % N;
    int t  = idx / N;
    int k2 = t % K2;
    int nb = t / K2;
    const float* s = src + ((long long)(nb * N + n)) * K + 2 * k2;
    float w0 = s[0], w1 = s[1];
    ulonglong2 v;
    v.x = pack2(w0, w0);
    v.y = pack2(w1, w1);
    g_wt[dst_off + idx] = v;
}

// Shared memory layout (floats)
#define SM_BUFE 0
#define SM_BUFT (256 * RPAD)
#define SM_BUFU (2 * 256 * RPAD)
#define SM_XS   (3 * 256 * RPAD)
#define SM_PROB (SM_XS + 4 * RPAD)
#define SM_YACC (SM_PROB + 7 * TB)
#define SM_SCR  (SM_YACC + TB)
#define SM_TOTAL (SM_SCR + 4 * TB)

// ---------------------------------------------------------------------------
// Fused GEMM layer, direct-LDG weights (pre-transposed + pre-duplicated).
//   in  : smem activations, [K][RPAD] feature-major
//   Wt  : g_wt region, [K/2][N] ulonglong2 (dup'd pairs)
//   out : smem activations, [N][RPAD]
//   ACT : 0 = sin(OMEGA*z), 1 = relu(z), 2 = relu(z + res)
// Thread tile: 8 rows (4 row-pairs, warp-owned) x NCOL cols (n = lane + 32j).
// Per 2 k-steps: 8 LDS.64 broadcast (a) + NCOL LDG.128 (w) + 8*NCOL FFMA2.
// No barriers inside the k-loop; one __syncthreads at layer end.
// PD = k-pair software-pipeline depth (K/2 % PD must be 0).
// ---------------------------------------------------------------------------
template <int K, int NCOL, int ACT, int PD>
static __device__ __forceinline__ void gemm_g(
    const float* __restrict__ in, const ulonglong2* __restrict__ Wt,
    const float* __restrict__ bias, float* __restrict__ out,
    const float* __restrict__ res)
{
    constexpr int N  = NCOL * 32;
    constexpr int K2 = K / 2;
    static_assert(K2 % PD == 0, "K2 % PD");

    const int tid  = threadIdx.x;
    const int lane = tid & 31;
    const int warp = tid >> 5;
    const int r0   = warp * 8;

    unsigned long long acc[4][NCOL];
#pragma unroll
    for (int i = 0; i < 4; i++)
#pragma unroll
        for (int j = 0; j < NCOL; j++) acc[i][j] = 0ull;

    const ulonglong2* Wp = Wt + lane;

    // prologue: fill PD k-pair stages
    ulonglong2 wreg[PD][NCOL];
#pragma unroll
    for (int d = 0; d < PD; d++)
#pragma unroll
        for (int j = 0; j < NCOL; j++)
            wreg[d][j] = __ldg(Wp + d * N + 32 * j);

    for (int k2 = 0; k2 < K2; k2 += PD) {
#pragma unroll
        for (int d = 0; d < PD; d++) {
            const int k = 2 * (k2 + d);
            const float* a0p = in + k * RPAD + r0;
            const float* a1p = a0p + RPAD;
            unsigned long long a0[4], a1[4];
#pragma unroll
            for (int i = 0; i < 4; i++) {         // broadcast LDS.64 row-pairs
                a0[i] = *(const unsigned long long*)(a0p + 2 * i);
                a1[i] = *(const unsigned long long*)(a1p + 2 * i);
            }
#pragma unroll
            for (int j = 0; j < NCOL; j++) {
                unsigned long long w0 = wreg[d][j].x;
                unsigned long long w1 = wreg[d][j].y;
#pragma unroll
                for (int i = 0; i < 4; i++) acc[i][j] = fma2(a0[i], w0, acc[i][j]);
#pragma unroll
                for (int i = 0; i < 4; i++) acc[i][j] = fma2(a1[i], w1, acc[i][j]);
            }
            // prefetch stage d for iteration k2+PD
            if (k2 + d + PD < K2) {
#pragma unroll
                for (int j = 0; j < NCOL; j++)
                    wreg[d][j] = __ldg(Wp + (k2 + d + PD) * N + 32 * j);
            }
        }
    }

    // epilogue: bias + activation, store transposed [n][row] as float2
#pragma unroll
    for (int j = 0; j < NCOL; j++) {
        int n = lane + 32 * j;
        float b = __ldg(bias + n);
#pragma unroll
        for (int i = 0; i < 4; i++) {
            float z0, z1;
            unpack2(acc[i][j], z0, z1);
            z0 += b; z1 += b;
            if (ACT == 0) {
                z0 = __sinf(OMEGA_F * z0);
                z1 = __sinf(OMEGA_F * z1);
            } else if (ACT == 1) {
                z0 = fmaxf(z0, 0.0f);
                z1 = fmaxf(z1, 0.0f);
            } else {
                float2 rv = *(const float2*)(res + n * RPAD + r0 + 2 * i);
                z0 = fmaxf(z0 + rv.x, 0.0f);
                z1 = fmaxf(z1 + rv.y, 0.0f);
            }
            *(float2*)(out + n * RPAD + r0 + 2 * i) = make_float2(z0, z1);
        }
    }
    __syncthreads();
}

// ---------------------------------------------------------------------------
__global__ void __launch_bounds__(NTHREADS, 1)
moe_inr_kernel(
    const float* __restrict__ x,
    const float* __restrict__ enc_s1_b, const float* __restrict__ enc_s2_b,
    const float* __restrict__ res_fc1_b, const float* __restrict__ res_fc2_b,
    const float* __restrict__ res_fc3_b,
    const float* __restrict__ pol_s1_b, const float* __restrict__ pol_s2_b,
    const float* __restrict__ gate_w, const float* __restrict__ gate_b,
    const float* __restrict__ exp_s1_b, const float* __restrict__ exp_s2_b,
    const float* __restrict__ exp_fin_w, const float* __restrict__ exp_fin_b,
    float* __restrict__ out)
{
    extern __shared__ float smem[];
    float* bufE  = smem + SM_BUFE;
    float* bufT  = smem + SM_BUFT;
    float* bufU  = smem + SM_BUFU;
    float* xs    = smem + SM_XS;
    float* probs = smem + SM_PROB;
    float* yacc  = smem + SM_YACC;
    float* scr   = smem + SM_SCR;

    const int tid = threadIdx.x;
    const long long rowbase = (long long)blockIdx.x * TB;

    // ---- load x tile: [4][RPAD] feature-major (256 = 64*4 exactly) ----
    {
        int r = tid >> 2, d = tid & 3;
        xs[d * RPAD + r] = x[(rowbase + r) * 4 + d];
    }
    __syncthreads();

    // ---- positional encoding -> bufT rows [0,64): col = d*16+f; f<8 sin else cos ----
    for (int idx = tid; idx < 64 * TB; idx += NTHREADS) {
        int r = idx & (TB - 1), c = idx / TB;
        int d = c >> 4, f = c & 15;
        float freq = exp2f((float)(f & 7)) * 3.14159265358979323846f;
        float ang  = xs[d * RPAD + r] * freq;
        bufT[c * RPAD + r] = (f < 8) ? sinf(ang) : cosf(ang);
    }
    __syncthreads();

    // ---- encoder ----
    gemm_g< 64, 4, 0, 2>(bufT, g_wt + OFF_ENC1, enc_s1_b,  bufU, nullptr); // sin ->128
    gemm_g<128, 8, 0, 2>(bufU, g_wt + OFF_ENC2, enc_s2_b,  bufE, nullptr); // sin -> h 256
    gemm_g<256, 4, 1, 2>(bufE, g_wt + OFF_RES1, res_fc1_b, bufT, nullptr); // relu ->128
    gemm_g<128, 4, 1, 2>(bufT, g_wt + OFF_RES2, res_fc2_b, bufU, nullptr); // relu ->128
    gemm_g<128, 8, 2, 2>(bufU, g_wt + OFF_RES3, res_fc3_b, bufE, bufE);    // relu(r+h)

    // ---- policy ----
    gemm_g<  4, 4, 0, 2>(xs,   g_wt + OFF_POL1, pol_s1_b,  bufT, nullptr); // sin ->128
    gemm_g<128, 4, 0, 2>(bufT, g_wt + OFF_POL2, pol_s2_b,  bufU, nullptr); // sin -> pf

    // ---- gate: logits over concat(enc_feat[256], pf[128]) ----
    float* gbuf = bufT;   // dead (pol_s2 consumed it); 16896 floats available
    for (int idx = tid; idx < 7 * 384; idx += NTHREADS) gbuf[idx] = gate_w[idx];
    __syncthreads();
    for (int idx = tid; idx < 7 * TB; idx += NTHREADS) {
        int r = idx & (TB - 1), c = idx / TB;
        const float* gw = gbuf + c * 384;
        float s = __ldg(gate_b + c);
        for (int k = 0; k < 256; k++) s += bufE[k * RPAD + r] * gw[k];
        for (int k = 0; k < 128; k++) s += bufU[k * RPAD + r] * gw[256 + k];
        probs[c * TB + r] = s;
    }
    __syncthreads();
    if (tid < TB) {
        int r = tid;
        float m = -1e30f;
        for (int c = 0; c < 7; c++) m = fmaxf(m, probs[c * TB + r]);
        float s = 0.0f, e[7];
        for (int c = 0; c < 7; c++) { e[c] = __expf(probs[c * TB + r] - m); s += e[c]; }
        float inv = 1.0f / s;
        for (int c = 0; c < 7; c++) probs[c * TB + r] = e[c] * inv;
        yacc[r] = 0.0f;
    }
    __syncthreads();

    // ---- experts ----
    for (int e = 0; e < 7; e++) {
        gemm_g<256, 8, 0, 2>(bufE, g_wt + OFF_EXP1 + e * 32768,
                             exp_s1_b + e * 256, bufT, nullptr);
        gemm_g<256, 8, 0, 2>(bufT, g_wt + OFF_EXP2 + e * 32768,
                             exp_s2_b + e * 256, bufU, nullptr);
        // final linear [256]->1, 4-way split reduction per row
        {
            int part = tid >> 6, r = tid & 63;
            const float* Wf = exp_fin_w + e * 256;
            float s = 0.0f;
            int k0 = part * 64;
            for (int k = k0; k < k0 + 64; k++) s += bufU[k * RPAD + r] * __ldg(Wf + k);
            scr[part * TB + r] = s;
        }
        __syncthreads();
        if (tid < TB) {
            int r = tid;
            float pred = scr[r] + scr[TB + r] + scr[2 * TB + r] + scr[3 * TB + r]
                       + __ldg(exp_fin_b + e);
            yacc[r] += probs[e * TB + r] * pred;
        }
        __syncthreads();
    }

    if (tid < TB) out[rowbase + tid] = yacc[tid];
}

// ---------------------------------------------------------------------------
static inline void launch_reformat(const float* src, int dst_off, int N, int K, int NB)
{
    int total = NB * (K / 2) * N;
    reformat_w<<<(total + 255) / 256, 256>>>(src, dst_off, N, K, NB);
}

extern "C" void kernel_launch(void* const* d_in, const int* in_sizes, int n_in,
                              void* d_out, int out_size)
{
    const float* x         = (const float*)d_in[0];
    const float* enc_s1_w  = (const float*)d_in[1];
    const float* enc_s1_b  = (const float*)d_in[2];
    const float* enc_s2_w  = (const float*)d_in[3];
    const float* enc_s2_b  = (const float*)d_in[4];
    const float* res_fc1_w = (const float*)d_in[5];
    const float* res_fc1_b = (const float*)d_in[6];
    const float* res_fc2_w = (const float*)d_in[7];
    const float* res_fc2_b = (const float*)d_in[8];
    const float* res_fc3_w = (const float*)d_in[9];
    const float* res_fc3_b = (const float*)d_in[10];
    const float* pol_s1_w  = (const float*)d_in[11];
    const float* pol_s1_b  = (const float*)d_in[12];
    const float* pol_s2_w  = (const float*)d_in[13];
    const float* pol_s2_b  = (const float*)d_in[14];
    const float* gate_w    = (const float*)d_in[15];
    const float* gate_b    = (const float*)d_in[16];
    const float* exp_s1_w  = (const float*)d_in[17];
    const float* exp_s1_b  = (const float*)d_in[18];
    const float* exp_s2_w  = (const float*)d_in[19];
    const float* exp_s2_b  = (const float*)d_in[20];
    const float* exp_fin_w = (const float*)d_in[21];
    const float* exp_fin_b = (const float*)d_in[22];

    // reformat all GEMM weights into g_wt (cheap; runs every launch, deterministic)
    launch_reformat(enc_s1_w,  OFF_ENC1, 128,  64, 1);
    launch_reformat(enc_s2_w,  OFF_ENC2, 256, 128, 1);
    launch_reformat(res_fc1_w, OFF_RES1, 128, 256, 1);
    launch_reformat(res_fc2_w, OFF_RES2, 128, 128, 1);
    launch_reformat(res_fc3_w, OFF_RES3, 256, 128, 1);
    launch_reformat(pol_s1_w,  OFF_POL1, 128,   4, 1);
    launch_reformat(pol_s2_w,  OFF_POL2, 128, 128, 1);
    launch_reformat(exp_s1_w,  OFF_EXP1, 256, 256, 7);
    launch_reformat(exp_s2_w,  OFF_EXP2, 256, 256, 7);

    int B = in_sizes[0] / 4;
    int grid = B / TB;
    size_t shmem = (size_t)SM_TOTAL * sizeof(float);

    cudaFuncSetAttribute(moe_inr_kernel,
                         cudaFuncAttributeMaxDynamicSharedMemorySize, (int)shmem);

    moe_inr_kernel<<<grid, NTHREADS, shmem>>>(
        x, enc_s1_b, enc_s2_b,
        res_fc1_b, res_fc2_b, res_fc3_b,
        pol_s1_b, pol_s2_b, gate_w, gate_b,
        exp_s1_b, exp_s2_b, exp_fin_w, exp_fin_b,
        (float*)d_out);
}